// round 1
// baseline (speedup 1.0000x reference)
#include <cuda_runtime.h>

// Problem constants
#define BB      2
#define NN      512
#define CC      64
#define HH      8
#define TN      128                 // n-values per tile
#define NTILES  (NN / TN)           // 4
#define THREADS 512
#define ROWF4   17                  // padded row stride in float4 (68 floats) -> conflict-free
#define DYN_BYTES (2 * TN * ROWF4 * 16)   // q tile + k tile = 69632 B

__device__ __forceinline__ float dot4(float4 a, float4 b, float acc) {
    acc = fmaf(a.x, b.x, acc);
    acc = fmaf(a.y, b.y, acc);
    acc = fmaf(a.z, b.z, acc);
    acc = fmaf(a.w, b.w, acc);
    return acc;
}

__global__ __launch_bounds__(THREADS)
void mha_fused_kernel(const float* __restrict__ q,
                      const float* __restrict__ k,
                      const float* __restrict__ roi,
                      const float* __restrict__ W,
                      const float* __restrict__ bias,
                      float* __restrict__ out)
{
    extern __shared__ float4 sm4[];
    float4* qs4 = sm4;                    // [TN][ROWF4]
    float4* ks4 = sm4 + TN * ROWF4;       // [TN][ROWF4]

    __shared__ float4 ws4[HH * 32];       // W: 8 heads x 128 floats (Wq|Wk)
    __shared__ float  bs[HH];
    __shared__ float  wsum[16][2];        // per-warp partial sums (h0,h1)

    const int tid = threadIdx.x;
    const int row = blockIdx.x;                   // b*N + m
    const size_t qk_off = (size_t)row * (NN * CC);
    const float* qrow = q   + qk_off;
    const float* krow = k   + qk_off;
    const float* rrow = roi + (size_t)row * NN;
    float*       orow = out + (size_t)row * (NN * HH);

    // Preload W (8x128 fp32 = 256 float4) and bias
    if (tid < HH * 32) ws4[tid] = ((const float4*)W)[tid];
    if (tid < HH)      bs[tid]  = bias[tid];

    const int nl = tid & (TN - 1);        // n within tile
    const int hp = tid >> 7;              // head pair 0..3 (constant per warp)
    const float4* w0 = ws4 + (2 * hp) * 32;       // head 2*hp   : [0..15]=Wq, [16..31]=Wk
    const float4* w1 = w0 + 32;                   // head 2*hp+1

    float a0[NTILES], a1[NTILES];
    float ps0 = 0.f, ps1 = 0.f;

    #pragma unroll
    for (int t = 0; t < NTILES; ++t) {
        // ---- coalesced tile load: 128 n x 64 c for q and k ----
        const float4* qg = (const float4*)(qrow + (size_t)t * TN * CC);
        const float4* kg = (const float4*)(krow + (size_t)t * TN * CC);
        #pragma unroll
        for (int i = tid; i < TN * 16; i += THREADS) {
            int n = i >> 4, c = i & 15;
            qs4[n * ROWF4 + c] = qg[i];
            ks4[n * ROWF4 + c] = kg[i];
        }
        __syncthreads();

        // ---- per-thread: one n, two heads ----
        const float4* qr = qs4 + nl * ROWF4;
        const float4* kr = ks4 + nl * ROWF4;
        float d0 = 0.f, d1 = 0.f;
        #pragma unroll
        for (int c = 0; c < 16; ++c) {
            float4 qv = qr[c];
            float4 kv = kr[c];
            d0 = dot4(qv, w0[c],      d0);
            d0 = dot4(kv, w0[16 + c], d0);
            d1 = dot4(qv, w1[c],      d1);
            d1 = dot4(kv, w1[16 + c], d1);
        }
        float rv = rrow[t * TN + nl];
        float v0 = __expf(d0 + bs[2 * hp])     * rv;
        float v1 = __expf(d1 + bs[2 * hp + 1]) * rv;
        a0[t] = v0; a1[t] = v1;
        ps0 += v0;  ps1 += v1;
        __syncthreads();   // protect tile buffers before next load / reuse
    }

    // ---- block reduction of per-head sums over n ----
    #pragma unroll
    for (int o = 16; o; o >>= 1) {
        ps0 += __shfl_xor_sync(0xffffffffu, ps0, o);
        ps1 += __shfl_xor_sync(0xffffffffu, ps1, o);
    }
    const int warp = tid >> 5;
    if ((tid & 31) == 0) { wsum[warp][0] = ps0; wsum[warp][1] = ps1; }
    __syncthreads();

    const int wb = 4 * hp;
    float s0 = wsum[wb][0] + wsum[wb + 1][0] + wsum[wb + 2][0] + wsum[wb + 3][0];
    float s1 = wsum[wb][1] + wsum[wb + 1][1] + wsum[wb + 2][1] + wsum[wb + 3][1];
    float inv0 = 1.0f / s0;
    float inv1 = 1.0f / s1;

    // ---- stage normalized attn into (reused) tile smem, then coalesced store ----
    float* ab = (float*)sm4;              // [512][8] = 16 KB, fits in q-tile region
    #pragma unroll
    for (int t = 0; t < NTILES; ++t) {
        int n = t * TN + nl;
        ab[n * HH + 2 * hp]     = a0[t] * inv0;
        ab[n * HH + 2 * hp + 1] = a1[t] * inv1;
    }
    __syncthreads();

    const float4* ab4 = (const float4*)ab;
    float4* og = (float4*)orow;
    #pragma unroll
    for (int i = tid; i < (NN * HH) / 4; i += THREADS)
        og[i] = ab4[i];
}

extern "C" void kernel_launch(void* const* d_in, const int* in_sizes, int n_in,
                              void* d_out, int out_size) {
    const float* q    = (const float*)d_in[0];
    const float* k    = (const float*)d_in[1];
    const float* roi  = (const float*)d_in[2];
    const float* W    = (const float*)d_in[3];
    const float* bias = (const float*)d_in[4];
    float* out = (float*)d_out;

    cudaFuncSetAttribute(mha_fused_kernel,
                         cudaFuncAttributeMaxDynamicSharedMemorySize, DYN_BYTES);
    mha_fused_kernel<<<BB * NN, THREADS, DYN_BYTES>>>(q, k, roi, W, bias, out);
}